// round 3
// baseline (speedup 1.0000x reference)
#include <cuda_runtime.h>
#include <cuda_bf16.h>

#define SEQ    2048
#define BATCH  64
#define D      256
#define CHUNKS 4
#define CHUNK_S (SEQ / CHUNKS)   // 512
#define HSIZE  4096
#define HMASK  (HSIZE - 1)
#define NT     256               // threads per CTA

#define H1 100
#define H2 150

// Scratch (device globals — no allocations allowed)
__device__ float g_partial[BATCH * CHUNKS * D];
__device__ int   g_count[BATCH];   // zero-init at load; self-resetting per run

__device__ __forceinline__ unsigned hash_tok(int tok) {
    return ((unsigned)tok * 2654435761u) & HMASK;
}

// ---------------------------------------------------------------------------
// Single fused kernel.
// Grid = BATCH*CHUNKS CTAs. Each CTA:
//   phase 1: TF-IDF weighted embedding gather for its (batch, chunk), write
//            partial pooled vector to global.
//   phase 2: threadfence + atomic ticket; the LAST CTA of each batch runs the
//            whole MLP for that batch (reduce -> L1 -> L2 -> L3 -> softmax).
// ---------------------------------------------------------------------------
__global__ __launch_bounds__(NT, 2)
void fused_kernel(const int*   __restrict__ x,
                  const float* __restrict__ emb,
                  const float* __restrict__ idf,
                  const float* __restrict__ W1, const float* __restrict__ b1,
                  const float* __restrict__ W2, const float* __restrict__ b2,
                  const float* __restrict__ W3, const float* __restrict__ b3,
                  float* __restrict__ out) {
    __shared__ int   tok_sh[SEQ];       // 8 KB
    __shared__ int   hkey[HSIZE];       // 16 KB
    __shared__ int   hcnt[HSIZE];       // 16 KB
    __shared__ float w_sh[CHUNK_S];     // 2 KB
    __shared__ float4 red4[4][D / 4];   // 4 KB
    __shared__ int   is_last_sh;
    // MLP shared buffers (reuse footprint is fine; they are distinct arrays)
    __shared__ float pooled[D];
    __shared__ float h1[H1];
    __shared__ float h2[H2];
    __shared__ float z[2];

    const int tid   = threadIdx.x;
    const int b     = blockIdx.x >> 2;
    const int chunk = blockIdx.x & 3;

    // ---------------- phase 1: pool ----------------
    #pragma unroll
    for (int i = tid; i < HSIZE; i += NT) {
        hkey[i] = -1;
        hcnt[i] = 0;
    }
    #pragma unroll
    for (int s = tid; s < SEQ; s += NT) {
        tok_sh[s] = x[s * BATCH + b];
    }
    __syncthreads();

    #pragma unroll
    for (int s = tid; s < SEQ; s += NT) {
        int tok = tok_sh[s];
        if (tok == 0) continue;
        unsigned h = hash_tok(tok);
        while (true) {
            int prev = atomicCAS(&hkey[h], -1, tok);
            if (prev == -1 || prev == tok) {
                atomicAdd(&hcnt[h], 1);
                break;
            }
            h = (h + 1) & HMASK;
        }
    }
    __syncthreads();

    const int base = chunk * CHUNK_S;
    for (int i = tid; i < CHUNK_S; i += NT) {
        int tok = tok_sh[base + i];
        float w = 0.0f;
        if (tok != 0) {
            unsigned h = hash_tok(tok);
            while (hkey[h] != tok) h = (h + 1) & HMASK;
            w = (float)hcnt[h] * __ldg(&idf[tok]);
        }
        w_sh[i] = w;
    }
    __syncthreads();

    const int sg = tid >> 6;
    const int dq = tid & 63;

    float4 acc = make_float4(0.f, 0.f, 0.f, 0.f);
    #pragma unroll 4
    for (int s = sg; s < CHUNK_S; s += 4) {
        float w  = w_sh[s];
        int  tok = tok_sh[base + s];
        float4 v = __ldg(reinterpret_cast<const float4*>(emb + (size_t)tok * D) + dq);
        acc.x += w * v.x;
        acc.y += w * v.y;
        acc.z += w * v.z;
        acc.w += w * v.w;
    }
    red4[sg][dq] = acc;
    __syncthreads();

    if (tid < D / 4) {
        float4 a = red4[0][tid];
        float4 c = red4[1][tid];
        float4 e = red4[2][tid];
        float4 f = red4[3][tid];
        float4 r = make_float4(a.x + c.x + e.x + f.x,
                               a.y + c.y + e.y + f.y,
                               a.z + c.z + e.z + f.z,
                               a.w + c.w + e.w + f.w);
        reinterpret_cast<float4*>(g_partial + ((size_t)b * CHUNKS + chunk) * D)[tid] = r;
    }

    // ---------------- phase 2: last-CTA ticket ----------------
    __threadfence();
    __syncthreads();
    if (tid == 0) {
        int prev = atomicAdd(&g_count[b], 1);
        is_last_sh = (prev == CHUNKS - 1);
        if (is_last_sh) g_count[b] = 0;   // self-reset for next run / replay
    }
    __syncthreads();
    if (!is_last_sh) return;

    // ---------------- phase 3: MLP for batch b (last CTA only) -------------
    // reduce 4 chunk partials -> pooled (read with .cg to bypass L1; data was
    // written by other SMs and lives in L2)
    {
        const float* p = g_partial + (size_t)b * CHUNKS * D;
        for (int i = tid; i < D; i += NT) {
            pooled[i] = __ldcg(p + i) + __ldcg(p + D + i) +
                        __ldcg(p + 2 * D + i) + __ldcg(p + 3 * D + i);
        }
    }
    __syncthreads();

    const int lane = tid & 31;
    const int wrp  = tid >> 5;   // 8 warps

    // L1: h1[j] = relu(dot(pooled, W1[j,:]) + b1[j]);  W1: [100, 256]
    for (int j = wrp; j < H1; j += 8) {
        const float* W = W1 + (size_t)j * D;
        float s0 = 0.f, s1 = 0.f;
        #pragma unroll
        for (int d = lane; d < D; d += 64) {
            s0 += pooled[d]      * __ldg(W + d);
            s1 += pooled[d + 32] * __ldg(W + d + 32);
        }
        float s = s0 + s1;
        #pragma unroll
        for (int o = 16; o; o >>= 1) s += __shfl_xor_sync(0xffffffffu, s, o);
        if (lane == 0) h1[j] = fmaxf(s + __ldg(b1 + j), 0.f);
    }
    __syncthreads();

    // L2: h2[j] = relu(dot(h1, W2[j,:]) + b2[j]);  W2: [150, 100]
    for (int j = wrp; j < H2; j += 8) {
        const float* W = W2 + (size_t)j * H1;
        float s = 0.f;
        #pragma unroll
        for (int d = lane; d < H1; d += 32) s += h1[d] * __ldg(W + d);
        #pragma unroll
        for (int o = 16; o; o >>= 1) s += __shfl_xor_sync(0xffffffffu, s, o);
        if (lane == 0) h2[j] = fmaxf(s + __ldg(b2 + j), 0.f);
    }
    __syncthreads();

    // L3: logits, then softmax
    if (wrp < 2) {
        const float* W = W3 + (size_t)wrp * H2;
        float s = 0.f;
        #pragma unroll
        for (int d = lane; d < H2; d += 32) s += h2[d] * __ldg(W + d);
        #pragma unroll
        for (int o = 16; o; o >>= 1) s += __shfl_xor_sync(0xffffffffu, s, o);
        if (lane == 0) z[wrp] = s + __ldg(b3 + wrp);
    }
    __syncthreads();

    if (tid == 0) {
        float m  = fmaxf(z[0], z[1]);
        float e0 = expf(z[0] - m);
        float e1 = expf(z[1] - m);
        float inv = 1.0f / (e0 + e1);
        out[b * 2 + 0] = e0 * inv;
        out[b * 2 + 1] = e1 * inv;
    }
}

extern "C" void kernel_launch(void* const* d_in, const int* in_sizes, int n_in,
                              void* d_out, int out_size) {
    const int*   x   = (const int*)  d_in[0];
    const float* emb = (const float*)d_in[1];
    const float* idf = (const float*)d_in[2];
    const float* W1  = (const float*)d_in[3];
    const float* b1  = (const float*)d_in[4];
    const float* W2  = (const float*)d_in[5];
    const float* b2  = (const float*)d_in[6];
    const float* W3  = (const float*)d_in[7];
    const float* b3  = (const float*)d_in[8];
    float* out = (float*)d_out;

    fused_kernel<<<BATCH * CHUNKS, NT>>>(x, emb, idf, W1, b1, W2, b2, W3, b3, out);
}